// round 2
// baseline (speedup 1.0000x reference)
#include <cuda_runtime.h>
#include <cstdint>
#include <math.h>

#define VOCAB  32000
#define EMBED  300
#define HIDDEN 512
#define G4     2048   // 4*HIDDEN
#define BATCH  256
#define SEQ    512
#define NOUT   7

// ---------------------------------------------------------------------------
// Device scratch (allocation-free rule: __device__ globals)
// gx layout: [s][b][g]  (step-contiguous so each timestep streams 2 MB)
// ---------------------------------------------------------------------------
__device__ float g_gx[(size_t)SEQ * BATCH * G4];   // 1 GiB
__device__ float g_h[2][BATCH * HIDDEN];
__device__ float g_c[2][BATCH * HIDDEN];

// ---------------------------------------------------------------------------
// Packed f32x2 helpers (ptxas never auto-fuses FFMA2; PTX-only path, 2x fp32)
// ---------------------------------------------------------------------------
__device__ __forceinline__ unsigned long long ffma2(unsigned long long a,
                                                    unsigned long long b,
                                                    unsigned long long c) {
    unsigned long long d;
    asm("fma.rn.f32x2 %0, %1, %2, %3;" : "=l"(d) : "l"(a), "l"(b), "l"(c));
    return d;
}
__device__ __forceinline__ unsigned long long dup_f32(float x) {
    unsigned long long d;
    asm("mov.b64 %0, {%1, %1};" : "=l"(d) : "f"(x));
    return d;
}
__device__ __forceinline__ float lo_f32(unsigned long long v) {
    return __uint_as_float((unsigned)(v & 0xffffffffull));
}
__device__ __forceinline__ float hi_f32(unsigned long long v) {
    return __uint_as_float((unsigned)(v >> 32));
}

// ---------------------------------------------------------------------------
// Kernel A: fused embedding gather + input projection GEMM
//   gx[r, g] = sum_e emb[tok(r), e] * W_ih[g, e] + b_ih[g]
//   r = s*256 + b,  M = 131072, N = 2048, K = 300
// Tile 128x128, 256 threads, micro-tile 8(m) x 8(n) done as 8 x 4 f32x2 pairs.
// ---------------------------------------------------------------------------
#define BM 128
#define BN 128
#define BK 16

__global__ __launch_bounds__(256, 2) void k_embed_inproj(
    const int* __restrict__ tokens, const float* __restrict__ emb,
    const float* __restrict__ W_ih, const float* __restrict__ b_ih)
{
    __shared__ float As[BK][BM];   // [kk][m]
    __shared__ float Bs[BK][BN];   // [kk][n]
    __shared__ int   tok_s[BM];

    const int n0  = blockIdx.x * BN;
    const int m0  = blockIdx.y * BM;
    const int tid = threadIdx.x;

    if (tid < BM) {
        int r = m0 + tid;
        int s = r >> 8;        // / 256
        int b = r & 255;
        tok_s[tid] = tokens[b * SEQ + s];
    }
    __syncthreads();

    const int tx = tid & 15;   // n direction
    const int ty = tid >> 4;   // m direction

    unsigned long long acc[8][4];
    #pragma unroll
    for (int i = 0; i < 8; i++)
        #pragma unroll
        for (int j = 0; j < 4; j++) acc[i][j] = 0ull;

    for (int k0 = 0; k0 < EMBED; k0 += BK) {
        // load A tile (gathered embedding rows), zero-padded past K=300
        #pragma unroll
        for (int x = 0; x < 8; x++) {
            int idx = tid + x * 256;          // 0..2047
            int m   = idx >> 4;
            int kk  = idx & 15;
            int e   = k0 + kk;
            int t   = tok_s[m];
            float v = 0.f;
            if (t != 0 && e < EMBED) v = emb[(size_t)t * EMBED + e];
            As[kk][m] = v;
        }
        // load B tile from W_ih [2048 x 300]
        #pragma unroll
        for (int x = 0; x < 8; x++) {
            int idx = tid + x * 256;
            int n   = idx >> 4;
            int kk  = idx & 15;
            int e   = k0 + kk;
            float v = 0.f;
            if (e < EMBED) v = W_ih[(size_t)(n0 + n) * EMBED + e];
            Bs[kk][n] = v;
        }
        __syncthreads();

        #pragma unroll
        for (int kk = 0; kk < BK; kk++) {
            float a[8];
            const float4* ap = (const float4*)&As[kk][ty * 8];
            float4 a0 = ap[0], a1 = ap[1];
            a[0]=a0.x; a[1]=a0.y; a[2]=a0.z; a[3]=a0.w;
            a[4]=a1.x; a[5]=a1.y; a[6]=a1.z; a[7]=a1.w;
            unsigned long long bv[4];
            const unsigned long long* bp =
                (const unsigned long long*)&Bs[kk][tx * 8];
            #pragma unroll
            for (int j = 0; j < 4; j++) bv[j] = bp[j];
            #pragma unroll
            for (int i = 0; i < 8; i++) {
                unsigned long long ad = dup_f32(a[i]);
                #pragma unroll
                for (int j = 0; j < 4; j++)
                    acc[i][j] = ffma2(ad, bv[j], acc[i][j]);
            }
        }
        __syncthreads();
    }

    // epilogue: add bias, store gx
    float bias[8];
    #pragma unroll
    for (int j = 0; j < 8; j++) bias[j] = b_ih[n0 + tx * 8 + j];

    #pragma unroll
    for (int i = 0; i < 8; i++) {
        int r = m0 + ty * 8 + i;
        size_t base = (size_t)r * G4 + n0 + tx * 8;
        #pragma unroll
        for (int j = 0; j < 4; j++) {
            g_gx[base + 2 * j]     = lo_f32(acc[i][j]) + bias[2 * j];
            g_gx[base + 2 * j + 1] = hi_f32(acc[i][j]) + bias[2 * j + 1];
        }
    }
}

// ---------------------------------------------------------------------------
// Kernel B: one LSTM timestep.
// CTA tile: 32 batches x 32 hidden-j (all 4 gates fused -> cell update local).
// Grid (16, 8) = 128 CTAs. Thread: jl = tid&31, bq = tid>>5 -> 4 b x 4 gates.
// K=512 processed in 16 chunks of 32 with register-staged software pipeline.
// ---------------------------------------------------------------------------
#define KC 32

__global__ __launch_bounds__(256) void k_lstm_step(
    int s, int src,
    const float* __restrict__ W_hh, const float* __restrict__ b_hh)
{
    __shared__ float Hs[32][KC];        // [b_local][kk]
    __shared__ float Ws[KC][129];       // [kk][g_local], padded vs bank conflicts

    const float* __restrict__ h_in = g_h[src];
    const float* __restrict__ c_in = g_c[src];
    float* __restrict__ h_out = g_h[src ^ 1];
    float* __restrict__ c_out = g_c[src ^ 1];

    const int j0  = blockIdx.x * 32;
    const int b0  = blockIdx.y * 32;
    const int tid = threadIdx.x;
    const int jl  = tid & 31;
    const int bq  = tid >> 5;
    const int j   = j0 + jl;

    // prefetch per-thread epilogue operands early (independent of GEMM)
    float bh[4], gxv[4][4], cv[4];
    #pragma unroll
    for (int g = 0; g < 4; g++) bh[g] = b_hh[g * HIDDEN + j];
    #pragma unroll
    for (int bb = 0; bb < 4; bb++) {
        int b = b0 + bq * 4 + bb;
        size_t gbase = ((size_t)s * BATCH + b) * G4;
        #pragma unroll
        for (int g = 0; g < 4; g++) gxv[bb][g] = g_gx[gbase + g * HIDDEN + j];
        cv[bb] = c_in[b * HIDDEN + j];
    }

    float acc[4][4];
    #pragma unroll
    for (int bb = 0; bb < 4; bb++)
        #pragma unroll
        for (int g = 0; g < 4; g++) acc[bb][g] = 0.f;

    // staging registers for the current chunk
    float hreg[4];    // 32*32 / 256
    float wreg[16];   // 128*32 / 256

    const int lkk = tid & 31;       // lane-contiguous k for coalesced LDG
    const int row8 = tid >> 5;

    // prologue: load chunk 0
    #pragma unroll
    for (int x = 0; x < 4; x++) {
        int bl = row8 + 8 * x;
        hreg[x] = h_in[(b0 + bl) * HIDDEN + lkk];
    }
    #pragma unroll
    for (int x = 0; x < 16; x++) {
        int gl = row8 + 8 * x;                       // 0..127
        int grow = (gl >> 5) * HIDDEN + j0 + (gl & 31);
        wreg[x] = W_hh[(size_t)grow * HIDDEN + lkk];
    }

    for (int ch = 0; ch < HIDDEN / KC; ch++) {
        __syncthreads();   // previous chunk's compute done
        #pragma unroll
        for (int x = 0; x < 4; x++) Hs[row8 + 8 * x][lkk] = hreg[x];
        #pragma unroll
        for (int x = 0; x < 16; x++) Ws[lkk][row8 + 8 * x] = wreg[x];
        __syncthreads();

        if (ch < HIDDEN / KC - 1) {
            int k0n = (ch + 1) * KC;
            #pragma unroll
            for (int x = 0; x < 4; x++) {
                int bl = row8 + 8 * x;
                hreg[x] = h_in[(b0 + bl) * HIDDEN + k0n + lkk];
            }
            #pragma unroll
            for (int x = 0; x < 16; x++) {
                int gl = row8 + 8 * x;
                int grow = (gl >> 5) * HIDDEN + j0 + (gl & 31);
                wreg[x] = W_hh[(size_t)grow * HIDDEN + k0n + lkk];
            }
        }

        #pragma unroll
        for (int kk = 0; kk < KC; kk++) {
            float wv[4];
            #pragma unroll
            for (int g = 0; g < 4; g++) wv[g] = Ws[kk][g * 32 + jl];
            #pragma unroll
            for (int bb = 0; bb < 4; bb++) {
                float hv = Hs[bq * 4 + bb][kk];
                #pragma unroll
                for (int g = 0; g < 4; g++) acc[bb][g] += hv * wv[g];
            }
        }
    }

    // cell update (i, f, g, o order per jnp.split / torch convention)
    #pragma unroll
    for (int bb = 0; bb < 4; bb++) {
        int b = b0 + bq * 4 + bb;
        float gi = acc[bb][0] + gxv[bb][0] + bh[0];
        float gf = acc[bb][1] + gxv[bb][1] + bh[1];
        float gg = acc[bb][2] + gxv[bb][2] + bh[2];
        float go = acc[bb][3] + gxv[bb][3] + bh[3];
        float ig = 1.f / (1.f + expf(-gi));
        float fg = 1.f / (1.f + expf(-gf));
        float gv = tanhf(gg);
        float og = 1.f / (1.f + expf(-go));
        float cn = fg * cv[bb] + ig * gv;
        c_out[b * HIDDEN + j] = cn;
        h_out[b * HIDDEN + j] = og * tanhf(cn);
    }
}

// ---------------------------------------------------------------------------
// Init: zero h0/c0 (buffer 0)
// ---------------------------------------------------------------------------
__global__ void k_init() {
    int i = blockIdx.x * blockDim.x + threadIdx.x;
    if (i < BATCH * HIDDEN) {
        g_h[0][i] = 0.f;
        g_c[0][i] = 0.f;
    }
}

// ---------------------------------------------------------------------------
// Kernel C: logits = h_T @ W_fc^T + b_fc   (h_T lives in g_h[0] after 512 steps)
// ---------------------------------------------------------------------------
__global__ __launch_bounds__(128) void k_fc(
    const float* __restrict__ W_fc, const float* __restrict__ b_fc,
    float* __restrict__ out)
{
    const int b   = blockIdx.x;
    const int tid = threadIdx.x;
    const float* __restrict__ h = g_h[0];

    float p[NOUT];
    #pragma unroll
    for (int o = 0; o < NOUT; o++) p[o] = 0.f;

    for (int jj = tid; jj < HIDDEN; jj += 128) {
        float hv = h[b * HIDDEN + jj];
        #pragma unroll
        for (int o = 0; o < NOUT; o++) p[o] += hv * W_fc[o * HIDDEN + jj];
    }

    __shared__ float red[NOUT][128];
    #pragma unroll
    for (int o = 0; o < NOUT; o++) red[o][tid] = p[o];
    __syncthreads();
    for (int st = 64; st > 0; st >>= 1) {
        if (tid < st) {
            #pragma unroll
            for (int o = 0; o < NOUT; o++) red[o][tid] += red[o][tid + st];
        }
        __syncthreads();
    }
    if (tid < NOUT) out[b * NOUT + tid] = red[tid][0] + b_fc[tid];
}

// ---------------------------------------------------------------------------
// Launch
// ---------------------------------------------------------------------------
extern "C" void kernel_launch(void* const* d_in, const int* in_sizes, int n_in,
                              void* d_out, int out_size)
{
    const int*   tokens = (const int*)  d_in[0];
    const float* emb    = (const float*)d_in[1];
    const float* W_ih   = (const float*)d_in[2];
    const float* b_ih   = (const float*)d_in[3];
    const float* W_hh   = (const float*)d_in[4];
    const float* b_hh   = (const float*)d_in[5];
    const float* W_fc   = (const float*)d_in[6];
    const float* b_fc   = (const float*)d_in[7];
    float* out = (float*)d_out;

    k_init<<<(BATCH * HIDDEN + 255) / 256, 256>>>();

    dim3 gA(G4 / BN, (BATCH * SEQ) / BM);   // (16, 1024)
    k_embed_inproj<<<gA, 256>>>(tokens, emb, W_ih, b_ih);

    dim3 gB(HIDDEN / 32, BATCH / 32);       // (16, 8) = 128 CTAs
    for (int s = 0; s < SEQ; s++)
        k_lstm_step<<<gB, 256>>>(s, s & 1, W_hh, b_hh);

    k_fc<<<BATCH, 128>>>(W_fc, b_fc, out);
}